// round 15
// baseline (speedup 1.0000x reference)
#include <cuda_runtime.h>
#include <cuda_bf16.h>
#include <cstdint>

#define T_LEN 256
#define HID   20
#define FFD   64
#define NROWS 32      // rows per CTA (2 pairs x 16)

// dynamic smem offsets (from 128-aligned base)
#define A1_OFF   0        // [32][64 bf16]: [h1_hi(20)|h1_lo(20)|h1_hi(20)|xh,xl,xh,pad]
#define A2_OFF   4096     // [32][64 bf16]
#define B1_OFF   8192     // [80][64 bf16] rows 0-39 units 0-9, 40-79 units 10-19
#define B2A_OFF  18432
#define B2B_OFF  28672
#define BQ1_OFF  38912    // 20 x float4
#define BQ2_OFF  39232
#define W1F_OFF  39552    // head W1 [64][20] f32
#define B1F_OFF  44672
#define W2F_OFF  44928
#define B2F_OFF  45184
#define DYN_BYTES 45568

#define SWZ(row, b) ((b) ^ (((row) & 7) << 4))
#define BARP(id) asm volatile("bar.sync %0, %1;" :: "r"(id), "r"(64) : "memory")

__device__ __forceinline__ float tanhap(float x) {
    float r; asm("tanh.approx.f32 %0, %1;" : "=f"(r) : "f"(x)); return r;
}
__device__ __forceinline__ float sigm(float x) {
    return fmaf(0.5f, tanhap(0.5f * x), 0.5f);
}
__device__ __forceinline__ uint32_t pack2(float hi_val, float lo_val) {
    uint32_t r;
    asm("cvt.rn.bf16x2.f32 %0, %1, %2;" : "=r"(r) : "f"(hi_val), "f"(lo_val));
    return r;
}
__device__ __forceinline__ void ldsm4(uint32_t* r, uint32_t a) {
    asm volatile("ldmatrix.sync.aligned.m8n8.x4.shared.b16 {%0,%1,%2,%3}, [%4];"
                 : "=r"(r[0]), "=r"(r[1]), "=r"(r[2]), "=r"(r[3]) : "r"(a));
}
__device__ __forceinline__ void ldsm2(uint32_t* r, uint32_t a) {
    asm volatile("ldmatrix.sync.aligned.m8n8.x2.shared.b16 {%0,%1}, [%2];"
                 : "=r"(r[0]), "=r"(r[1]) : "r"(a));
}
__device__ __forceinline__ void mma16816(float* c, const uint32_t* a, const uint32_t* b) {
    asm volatile(
        "mma.sync.aligned.m16n8k16.row.col.f32.bf16.bf16.f32 "
        "{%0,%1,%2,%3}, {%4,%5,%6,%7}, {%8,%9}, {%0,%1,%2,%3};"
        : "+f"(c[0]), "+f"(c[1]), "+f"(c[2]), "+f"(c[3])
        : "r"(a[0]), "r"(a[1]), "r"(a[2]), "r"(a[3]), "r"(b[0]), "r"(b[1]));
}

// A fragment address for a 16-row tile at 'base', k-step ks
__device__ __forceinline__ uint32_t a_addr(uint32_t base, int ks, int lane) {
    int sub = lane >> 3, lr = lane & 7;
    int row = ((sub & 1) << 3) + lr;
    int cb  = ks * 32 + ((sub >> 1) << 4);
    return base + row * 128 + SWZ(row, cb);
}
// B x4 fragment address for n-tile pair 2np within the 40-row half tile
__device__ __forceinline__ uint32_t b_addr(uint32_t base, int np, int ks, int lane) {
    int sub = lane >> 3, lr = lane & 7;
    int row = np * 16 + ((sub >> 1) << 3) + lr;
    int cb  = ks * 32 + ((sub & 1) << 4);
    return base + row * 128 + SWZ(row, cb);
}
// B x2 fragment address for the 5th n-tile (rows 32-39 of the half tile)
__device__ __forceinline__ uint32_t b_addr2(uint32_t base, int ks, int lane) {
    int lr = lane & 7;
    int q  = (lane >> 3) & 1;
    int row = 32 + lr;
    int cb  = ks * 32 + (q << 4);
    return base + row * 128 + SWZ(row, cb);
}

// K=64 pass, M=16, N=40, B resident in regs (bf[ks*10 + 2*nt])
__device__ __forceinline__ void gemm_regB(float cacc[5][4], uint32_t aB,
                                          const uint32_t* bf, int lane) {
#pragma unroll
    for (int ks = 0; ks < 4; ks++) {
        uint32_t a0[4];
        ldsm4(a0, a_addr(aB, ks, lane));
        const uint32_t* b = bf + ks * 10;
        mma16816(cacc[0], a0, b + 0);
        mma16816(cacc[1], a0, b + 2);
        mma16816(cacc[2], a0, b + 4);
        mma16816(cacc[3], a0, b + 6);
        mma16816(cacc[4], a0, b + 8);
    }
}
// K=64 pass, M=16, N=40, B streamed from smem half-tile
__device__ __forceinline__ void gemm_smemB(float cacc[5][4], uint32_t aB, uint32_t bB, int lane) {
#pragma unroll
    for (int ks = 0; ks < 4; ks++) {
        uint32_t a0[4];
        ldsm4(a0, a_addr(aB, ks, lane));
        uint32_t b01[4], b23[4], b4[2];
        ldsm4(b01, b_addr(bB, 0, ks, lane));
        ldsm4(b23, b_addr(bB, 1, ks, lane));
        ldsm2(b4,  b_addr2(bB, ks, lane));
        mma16816(cacc[0], a0, b01);
        mma16816(cacc[1], a0, b01 + 2);
        mma16816(cacc[2], a0, b23);
        mma16816(cacc[3], a0, b23 + 2);
        mma16816(cacc[4], a0, b4);
    }
}

// Epilogue: unit u = 2*nt + s + 10*half; exchange with lane^1; retire row rEp.
__device__ __forceinline__ void epilogue(float cacc[5][4], const float4* bq, float* cs,
                                         char* arow, int rEp, int odd, int s, int half) {
#pragma unroll
    for (int nt = 0; nt < 5; nt++) {
        float s0 = odd ? cacc[nt][0] : cacc[nt][2];
        float s1 = odd ? cacc[nt][1] : cacc[nt][3];
        float p0 = __shfl_xor_sync(0xFFFFFFFFu, s0, 1);
        float p1 = __shfl_xor_sync(0xFFFFFFFFu, s1, 1);
        float zi = odd ? p0 : cacc[nt][0];
        float zf = odd ? p1 : cacc[nt][1];
        float zg = odd ? cacc[nt][2] : p0;
        float zo = odd ? cacc[nt][3] : p1;
        int u = 2 * nt + s + 10 * half;
        float4 b4 = bq[u];
        float ii = sigm(zi + b4.x);
        float ff = sigm(zf + b4.y);
        float gg = tanhap(zg + b4.z);
        float oo = sigm(zo + b4.w);
        float cc = fmaf(ff, cs[nt], ii * gg); cs[nt] = cc;
        float h = oo * tanhap(cc);
        __nv_bfloat16 hh16 = __float2bfloat16(h);
        float hf = __bfloat162float(hh16);
        __nv_bfloat16 hl16 = __float2bfloat16(h - hf);
        uint16_t hiu = __bfloat16_as_ushort(hh16);
        uint16_t lou = __bfloat16_as_ushort(hl16);
        *(uint16_t*)(arow + SWZ(rEp, 2 * u))      = hiu;   // hi    (cols 0-19)
        *(uint16_t*)(arow + SWZ(rEp, 40 + 2 * u)) = lou;   // lo    (cols 20-39)
        *(uint16_t*)(arow + SWZ(rEp, 80 + 2 * u)) = hiu;   // hi dup (cols 40-59)
    }
}

__global__ void __launch_bounds__(128, 2) lstm2_mma_kernel(
    const float* __restrict__ diag,
    const float* __restrict__ W_ih1, const float* __restrict__ W_hh1,
    const float* __restrict__ b_ih1, const float* __restrict__ b_hh1,
    const float* __restrict__ W_ih2, const float* __restrict__ W_hh2,
    const float* __restrict__ b_ih2, const float* __restrict__ b_hh2,
    const float* __restrict__ W1,   const float* __restrict__ b1,
    const float* __restrict__ W2,   const float* __restrict__ b2,
    float* __restrict__ out, int rows)
{
    extern __shared__ char rawsm[];
    char* sm = (char*)(((uintptr_t)rawsm + 127) & ~(uintptr_t)127);
    const uint32_t smb = (uint32_t)__cvta_generic_to_shared(sm);

    const int tid    = threadIdx.x;
    const int lane   = tid & 31;
    const int wid    = tid >> 5;
    const int pairId = wid >> 1;       // 2 pairs x 16 rows
    const int half   = wid & 1;        // 0: units 0-9, 1: units 10-19
    const int Rw     = pairId * 16;

    // ---- zero A1+A2 (8 KB) ----
    for (int i = tid; i < 8192 / 4; i += 128) *(uint32_t*)(sm + A1_OFF + 4 * i) = 0;

    // ---- stage B tiles: row n: hf=(n>=40), nl=n-40*hf, wr=(nl&3)*20+(nl>>2)+10*hf ----
    for (int idx = tid; idx < 80 * 64; idx += 128) {
        int n = idx >> 6, k = idx & 63;
        int off = n * 128 + SWZ(n, 2 * k);
        int hf2 = (n >= 40);
        int nl  = n - 40 * hf2;
        int wr  = (nl & 3) * HID + (nl >> 2) + 10 * hf2;
        float v; bool lo;
        if (k < 20)      { v = W_hh1[wr * HID + k];      lo = false; }
        else if (k < 40) { v = W_hh1[wr * HID + k - 20]; lo = false; }
        else if (k < 60) { v = W_hh1[wr * HID + k - 40]; lo = true;  }
        else if (k < 62) { v = W_ih1[wr];                lo = false; }
        else if (k == 62){ v = W_ih1[wr];                lo = true;  }
        else             { v = 0.f;                      lo = false; }
        __nv_bfloat16 vh = __float2bfloat16(v);
        *(__nv_bfloat16*)(sm + B1_OFF + off) =
            lo ? __float2bfloat16(v - __bfloat162float(vh)) : vh;
        float va = (k < 20) ? W_ih2[wr * HID + k] : (k < 40) ? W_ih2[wr * HID + k - 20]
                 : (k < 60) ? W_ih2[wr * HID + k - 40] : 0.f;
        float vb = (k < 20) ? W_hh2[wr * HID + k] : (k < 40) ? W_hh2[wr * HID + k - 20]
                 : (k < 60) ? W_hh2[wr * HID + k - 40] : 0.f;
        bool lo2 = (k >= 40 && k < 60);
        __nv_bfloat16 vah = __float2bfloat16(va), vbh = __float2bfloat16(vb);
        *(__nv_bfloat16*)(sm + B2A_OFF + off) =
            lo2 ? __float2bfloat16(va - __bfloat162float(vah)) : vah;
        *(__nv_bfloat16*)(sm + B2B_OFF + off) =
            lo2 ? __float2bfloat16(vb - __bfloat162float(vbh)) : vbh;
    }
    for (int j = tid; j < HID; j += 128) {
        ((float4*)(sm + BQ1_OFF))[j] = make_float4(
            b_ih1[j] + b_hh1[j], b_ih1[HID + j] + b_hh1[HID + j],
            b_ih1[2*HID + j] + b_hh1[2*HID + j], b_ih1[3*HID + j] + b_hh1[3*HID + j]);
        ((float4*)(sm + BQ2_OFF))[j] = make_float4(
            b_ih2[j] + b_hh2[j], b_ih2[HID + j] + b_hh2[HID + j],
            b_ih2[2*HID + j] + b_hh2[2*HID + j], b_ih2[3*HID + j] + b_hh2[3*HID + j]);
    }
    for (int i = tid; i < FFD * HID; i += 128) ((float*)(sm + W1F_OFF))[i] = W1[i];
    for (int i = tid; i < FFD; i += 128) {
        ((float*)(sm + B1F_OFF))[i] = b1[i];
        ((float*)(sm + W2F_OFF))[i] = W2[i];
    }
    if (tid == 0) *((float*)(sm + B2F_OFF)) = b2[0];
    __syncthreads();

    // ---- preload B1 + B2a fragments into registers (time-invariant) ----
    const uint32_t B1h  = smb + B1_OFF  + half * 40 * 128;
    const uint32_t B2Ah = smb + B2A_OFF + half * 40 * 128;
    const uint32_t B2Bh = smb + B2B_OFF + half * 40 * 128;
    uint32_t B1f[40], B2af[40];
#pragma unroll
    for (int ks = 0; ks < 4; ks++) {
        ldsm4(B1f  + ks * 10 + 0, b_addr(B1h,  0, ks, lane));
        ldsm4(B1f  + ks * 10 + 4, b_addr(B1h,  1, ks, lane));
        ldsm2(B1f  + ks * 10 + 8, b_addr2(B1h,  ks, lane));
        ldsm4(B2af + ks * 10 + 0, b_addr(B2Ah, 0, ks, lane));
        ldsm4(B2af + ks * 10 + 4, b_addr(B2Ah, 1, ks, lane));
        ldsm2(B2af + ks * 10 + 8, b_addr2(B2Ah, ks, lane));
    }

    const int m    = lane & 3;
    const int odd  = m & 1;
    const int s    = m >> 1;
    const int rEp  = Rw + (lane >> 2) + (odd ? 8 : 0);   // row this thread retires
    const int rg   = blockIdx.x * NROWS + rEp;
    const float* __restrict__ xrow = diag + (size_t)min(rg, rows - 1) * T_LEN;
    char* A1row = sm + A1_OFF + rEp * 128;
    char* A2row = sm + A2_OFF + rEp * 128;

    // stage x_0 (half0 warps; m<2 covers all 16 rows of the pair)
    if (half == 0 && m < 2) {
        float xv = __ldg(xrow);
        __nv_bfloat16 xh = __float2bfloat16(xv);
        float xhf = __bfloat162float(xh);
        *(uint32_t*)(A1row + SWZ(rEp, 120)) = pack2(xv - xhf, xhf);
        *(uint32_t*)(A1row + SWZ(rEp, 124)) = (uint32_t)__bfloat16_as_ushort(xh);
    }
    __syncthreads();

    const uint32_t A1w = smb + A1_OFF + Rw * 128;
    const uint32_t A2w = smb + A2_OFF + Rw * 128;
    const float4* bq1 = (const float4*)(sm + BQ1_OFF);
    const float4* bq2 = (const float4*)(sm + BQ2_OFF);
    const int barId = 1 + pairId;

    float c1s[5], c2s[5];
#pragma unroll
    for (int j = 0; j < 5; j++) { c1s[j] = 0.f; c2s[j] = 0.f; }

#pragma unroll 1
    for (int t = 0; t < T_LEN; t++) {
        float cacc[5][4];

        // ---- layer 1: z1 = A1 x B1half^T (resident B) ----
#pragma unroll
        for (int nt = 0; nt < 5; nt++)
#pragma unroll
            for (int e = 0; e < 4; e++) cacc[nt][e] = 0.f;
        gemm_regB(cacc, A1w, B1f, lane);
        BARP(barId);                                   // A1 reads done (both warps)
        epilogue(cacc, bq1, c1s, A1row, rEp, odd, s, half);  // h1(t) -> A1
        if (t + 1 < T_LEN && half == 0 && m < 2) {     // stage x_{t+1} (zeros in B cols 60-63)
            float xv = __ldg(xrow + t + 1);
            __nv_bfloat16 xh = __float2bfloat16(xv);
            float xhf = __bfloat162float(xh);
            *(uint32_t*)(A1row + SWZ(rEp, 120)) = pack2(xv - xhf, xhf);
            *(uint32_t*)(A1row + SWZ(rEp, 124)) = (uint32_t)__bfloat16_as_ushort(xh);
        }
        BARP(barId);                                   // A1 writes visible

        // ---- layer 2: z2 = A1 x B2a^T (resident) + A2 x B2b^T (smem) ----
#pragma unroll
        for (int nt = 0; nt < 5; nt++)
#pragma unroll
            for (int e = 0; e < 4; e++) cacc[nt][e] = 0.f;
        gemm_regB(cacc, A1w, B2af, lane);
        gemm_smemB(cacc, A2w, B2Bh, lane);
        BARP(barId);                                   // A2 reads done
        epilogue(cacc, bq2, c2s, A2row, rEp, odd, s, half);  // h2(t) -> A2
        // A2 writes ordered before next-iteration layer2 reads by next iter's two bars
    }
    __syncthreads();

    // ---- head (half0 warps): h2 = hi+lo from A2; FF split by s, combine over lane^2 ----
    if (half == 0) {
        const float* W1f = (const float*)(sm + W1F_OFF);
        const float* b1f = (const float*)(sm + B1F_OFF);
        const float* W2f = (const float*)(sm + W2F_OFF);
        const float b2v  = *((const float*)(sm + B2F_OFF));
        float h2f[HID];
#pragma unroll
        for (int q = 0; q < 10; q++) {
            uint32_t hi = *(uint32_t*)(A2row + SWZ(rEp, 4 * q));
            uint32_t lo = *(uint32_t*)(A2row + SWZ(rEp, 40 + 4 * q));
            h2f[2*q]     = __uint_as_float(hi << 16) + __uint_as_float(lo << 16);
            h2f[2*q + 1] = __uint_as_float(hi & 0xFFFF0000u) + __uint_as_float(lo & 0xFFFF0000u);
        }
        float acc2 = (s == 0) ? b2v : 0.0f;
        const int n0 = s * 32;
#pragma unroll 1
        for (int n = n0; n < n0 + 32; n++) {
            float a = b1f[n];
#pragma unroll
            for (int k = 0; k < HID; k++) a = fmaf(W1f[n * HID + k], h2f[k], a);
            acc2 = fmaf(W2f[n], fmaxf(a, 0.0f), acc2);
        }
        acc2 += __shfl_xor_sync(0xFFFFFFFFu, acc2, 2);
        if (s == 0 && rg < rows) out[rg] = fmaxf(acc2, 0.0f);
    }
}

extern "C" void kernel_launch(void* const* d_in, const int* in_sizes, int n_in,
                              void* d_out, int out_size) {
    const float* diag  = (const float*)d_in[0];
    const float* W_ih1 = (const float*)d_in[1];
    const float* W_hh1 = (const float*)d_in[2];
    const float* b_ih1 = (const float*)d_in[3];
    const float* b_hh1 = (const float*)d_in[4];
    const float* W_ih2 = (const float*)d_in[5];
    const float* W_hh2 = (const float*)d_in[6];
    const float* b_ih2 = (const float*)d_in[7];
    const float* b_hh2 = (const float*)d_in[8];
    const float* W1    = (const float*)d_in[9];
    const float* b1    = (const float*)d_in[10];
    const float* W2    = (const float*)d_in[11];
    const float* b2    = (const float*)d_in[12];

    int rows = out_size;                     // 131072
    int blocks = (rows + NROWS - 1) / NROWS; // 4096

    cudaFuncSetAttribute(lstm2_mma_kernel,
                         cudaFuncAttributeMaxDynamicSharedMemorySize, DYN_BYTES);

    lstm2_mma_kernel<<<blocks, 128, DYN_BYTES>>>(
        diag, W_ih1, W_hh1, b_ih1, b_hh1,
        W_ih2, W_hh2, b_ih2, b_hh2,
        W1, b1, W2, b2, (float*)d_out, rows);
}

// round 16
// speedup vs baseline: 3.0805x; 3.0805x over previous
#include <cuda_runtime.h>
#include <cuda_fp16.h>
#include <cstdint>

#define T_LEN 256
#define HID   20
#define FFD   64

// dynamic smem offsets (from 128-aligned base); 128 rows per CTA
#define A1_OFF   0        // [128][128B] fp16 cols: h1(0-19), x(20), 1.0(21), 0(22-31)
#define A2_OFF   16384    // [128][128B] fp16 cols: h1(0-19), h2(20-39), 1.0(40), 0(41-47)
#define B1_OFF   32768    // [80][128B] fp16: Whh1(0-19), Wih1(20), bias1(21), 0
#define B2_OFF   43008    // [80][128B] fp16: Wih2(0-19), Whh2(20-39), bias2(40), 0
#define H2F_OFF  53248    // [128][20] f32 h2 (for head) = 10240
#define W1F_OFF  63488    // head W1 [64][20] f32
#define B1F_OFF  68608
#define W2F_OFF  68864
#define B2F_OFF  69120
#define DYN_BYTES 69632

#define SWZ(row, b) ((b) ^ (((row) & 7) << 4))

__device__ __forceinline__ float tanhap(float x) {
    float r; asm("tanh.approx.f32 %0, %1;" : "=f"(r) : "f"(x)); return r;
}
__device__ __forceinline__ float sigm(float x) {
    return fmaf(0.5f, tanhap(0.5f * x), 0.5f);
}
__device__ __forceinline__ void ldsm4(uint32_t* r, uint32_t a) {
    asm volatile("ldmatrix.sync.aligned.m8n8.x4.shared.b16 {%0,%1,%2,%3}, [%4];"
                 : "=r"(r[0]), "=r"(r[1]), "=r"(r[2]), "=r"(r[3]) : "r"(a));
}
__device__ __forceinline__ void mma16816(float* c, const uint32_t* a, const uint32_t* b) {
    asm volatile(
        "mma.sync.aligned.m16n8k16.row.col.f32.f16.f16.f32 "
        "{%0,%1,%2,%3}, {%4,%5,%6,%7}, {%8,%9}, {%0,%1,%2,%3};"
        : "+f"(c[0]), "+f"(c[1]), "+f"(c[2]), "+f"(c[3])
        : "r"(a[0]), "r"(a[1]), "r"(a[2]), "r"(a[3]), "r"(b[0]), "r"(b[1]));
}

// A fragment address for a 16-row tile at 'base', k-step ks
__device__ __forceinline__ uint32_t a_addr(uint32_t base, int ks, int lane) {
    int sub = lane >> 3, lr = lane & 7;
    int row = ((sub & 1) << 3) + lr;
    int cb  = ks * 32 + ((sub >> 1) << 4);
    return base + row * 128 + SWZ(row, cb);
}
// B fragment address: regs {0,1}=n-tile 2np, {2,3}=2np+1
__device__ __forceinline__ uint32_t b_addr(uint32_t base, int np, int ks, int lane) {
    int sub = lane >> 3, lr = lane & 7;
    int row = np * 16 + ((sub >> 1) << 3) + lr;
    int cb  = ks * 32 + ((sub & 1) << 4);
    return base + row * 128 + SWZ(row, cb);
}

// GEMM pass, M=16, N=80, K = NKS*16; accumulate into cacc[10][4]
template<int NKS>
__device__ __forceinline__ void gemm(float cacc[10][4], uint32_t aB, uint32_t bB, int lane) {
#pragma unroll
    for (int ks = 0; ks < NKS; ks++) {
        uint32_t a0[4];
        ldsm4(a0, a_addr(aB, ks, lane));
#pragma unroll
        for (int np = 0; np < 5; np++) {
            uint32_t b[4];
            ldsm4(b, b_addr(bB, np, ks, lane));
            mma16816(cacc[2*np],     a0, b);
            mma16816(cacc[2*np + 1], a0, b + 2);
        }
    }
}

// Register epilogue (z already includes bias via the 1.0 column).
// Thread m=lane&3: s=m>>1, odd=m&1; unit u = nt + 10*s; retires row rEp.
// d0 (and optionally d1): fp16 h destinations at byte base; h2f32: optional fp32 copy.
__device__ __forceinline__ void epilogue(float cacc[10][4], float* cs,
                                         char* d0, char* d1, int base,
                                         int rEp, int odd, int s, float* h2f32) {
#pragma unroll
    for (int a = 0; a < 5; a++) {
        float h01[2];
#pragma unroll
        for (int e = 0; e < 2; e++) {
            int nt = 2 * a + e;
            float s0 = odd ? cacc[nt][0] : cacc[nt][2];
            float s1 = odd ? cacc[nt][1] : cacc[nt][3];
            float p0 = __shfl_xor_sync(0xFFFFFFFFu, s0, 1);
            float p1 = __shfl_xor_sync(0xFFFFFFFFu, s1, 1);
            float zi = odd ? p0 : cacc[nt][0];
            float zf = odd ? p1 : cacc[nt][1];
            float zg = odd ? cacc[nt][2] : p0;
            float zo = odd ? cacc[nt][3] : p1;
            float ii = sigm(zi);
            float ff = sigm(zf);
            float gg = tanhap(zg);
            float oo = sigm(zo);
            float cc = fmaf(ff, cs[nt], ii * gg); cs[nt] = cc;
            h01[e] = oo * tanhap(cc);
        }
        uint32_t packed;
        asm("cvt.rn.f16x2.f32 %0, %1, %2;" : "=r"(packed) : "f"(h01[1]), "f"(h01[0]));
        int by = base + 4 * a + 20 * s;
        *(uint32_t*)(d0 + SWZ(rEp, by)) = packed;
        if (d1) *(uint32_t*)(d1 + SWZ(rEp, by)) = packed;
        if (h2f32) *(float2*)(h2f32 + 2 * a + 10 * s) = make_float2(h01[0], h01[1]);
    }
}

__global__ void __launch_bounds__(256, 2) lstm2_mma_kernel(
    const float* __restrict__ diag,
    const float* __restrict__ W_ih1, const float* __restrict__ W_hh1,
    const float* __restrict__ b_ih1, const float* __restrict__ b_hh1,
    const float* __restrict__ W_ih2, const float* __restrict__ W_hh2,
    const float* __restrict__ b_ih2, const float* __restrict__ b_hh2,
    const float* __restrict__ W1,   const float* __restrict__ b1,
    const float* __restrict__ W2,   const float* __restrict__ b2,
    float* __restrict__ out, int rows)
{
    extern __shared__ char rawsm[];
    char* sm = (char*)(((uintptr_t)rawsm + 127) & ~(uintptr_t)127);
    const uint32_t smb = (uint32_t)__cvta_generic_to_shared(sm);

    const int tid  = threadIdx.x;
    const int lane = tid & 31;
    const int wid  = tid >> 5;
    const int Rw   = wid * 16;           // 16 rows per warp, 8 warps = 128 rows

    // ---- zero A1+A2+B1+B2 (53248 B) ----
    for (int i = tid; i < 53248 / 4; i += 256) *(uint32_t*)(sm + 4 * i) = 0;
    __syncthreads();

    // ---- stage B tiles (fp16): row n <-> (gate = n&3, unit = (n>>3)+10*((n>>2)&1)) ----
    for (int idx = tid; idx < 80 * 41; idx += 256) {
        int n = idx / 41, k = idx % 41;
        int wr = (n & 3) * HID + ((n >> 3) + 10 * ((n >> 2) & 1));
        // B2: cols 0-19 Wih2, 20-39 Whh2, 40 bias2
        float v2 = (k < 20) ? W_ih2[wr * HID + k]
                 : (k < 40) ? W_hh2[wr * HID + (k - 20)]
                 :            (b_ih2[wr] + b_hh2[wr]);
        *(__half*)(sm + B2_OFF + n * 128 + SWZ(n, 2 * k)) = __float2half_rn(v2);
        // B1: cols 0-19 Whh1, 20 Wih1, 21 bias1
        if (k < 22) {
            float v1 = (k < 20) ? W_hh1[wr * HID + k]
                     : (k == 20) ? W_ih1[wr]
                     :             (b_ih1[wr] + b_hh1[wr]);
            *(__half*)(sm + B1_OFF + n * 128 + SWZ(n, 2 * k)) = __float2half_rn(v1);
        }
    }
    // A2 col 40 = 1.0 (bias activator), per row
    for (int r = tid; r < 128; r += 256)
        *(__half*)(sm + A2_OFF + r * 128 + SWZ(r, 80)) = __float2half_rn(1.0f);
    // head weights
    for (int i = tid; i < FFD * HID; i += 256) ((float*)(sm + W1F_OFF))[i] = W1[i];
    for (int i = tid; i < FFD; i += 256) {
        ((float*)(sm + B1F_OFF))[i] = b1[i];
        ((float*)(sm + W2F_OFF))[i] = W2[i];
    }
    if (tid == 0) *((float*)(sm + B2F_OFF)) = b2[0];
    __syncthreads();

    const int m    = lane & 3;
    const int odd  = m & 1;
    const int s    = m >> 1;
    const int rEp  = Rw + (lane >> 2) + (odd ? 8 : 0);  // row this thread retires
    const int rg   = blockIdx.x * 128 + rEp;
    const float* __restrict__ xrow = diag + (size_t)min(rg, rows - 1) * T_LEN;
    char* A1row = sm + A1_OFF + rEp * 128;
    char* A2row = sm + A2_OFF + rEp * 128;
    float* h2row = (float*)(sm + H2F_OFF) + rEp * HID;

    // stage x_0: A1 cols 20 (x) and 21 (1.0) in one u32
    if (m < 2) {
        float xv = __ldg(xrow);
        uint32_t xp = 0x3C000000u | (uint32_t)__half_as_ushort(__float2half_rn(xv));
        *(uint32_t*)(A1row + SWZ(rEp, 40)) = xp;
    }
    __syncthreads();

    const uint32_t A1w = smb + A1_OFF + Rw * 128;
    const uint32_t A2w = smb + A2_OFF + Rw * 128;

    float c1s[10], c2s[10];
#pragma unroll
    for (int j = 0; j < 10; j++) { c1s[j] = 0.f; c2s[j] = 0.f; }

#pragma unroll 1
    for (int t = 0; t < T_LEN; t++) {
        float cacc[10][4];

        // ---- layer 1: z1 = A1[K=32] x B1^T (bias included) ----
#pragma unroll
        for (int nt = 0; nt < 10; nt++)
#pragma unroll
            for (int e = 0; e < 4; e++) cacc[nt][e] = 0.f;
        gemm<2>(cacc, A1w, smb + B1_OFF, lane);
        // h1(t) -> A1 cols 0-19 AND A2 cols 0-19
        epilogue(cacc, c1s, A1row, A2row, 0, rEp, odd, s, nullptr);
        __syncwarp();

        // ---- layer 2: z2 = A2[K=48] x B2^T (h1|h2|bias) ----
#pragma unroll
        for (int nt = 0; nt < 10; nt++)
#pragma unroll
            for (int e = 0; e < 4; e++) cacc[nt][e] = 0.f;
        gemm<3>(cacc, A2w, smb + B2_OFF, lane);
        // h2(t) -> A2 cols 20-39 (+ fp32 copy for head)
        epilogue(cacc, c2s, A2row, nullptr, 40, rEp, odd, s, h2row);
        if (t + 1 < T_LEN && m < 2) {   // stage x_{t+1} (keeps col 21 = 1.0)
            float xv = __ldg(xrow + t + 1);
            uint32_t xp = 0x3C000000u | (uint32_t)__half_as_ushort(__float2half_rn(xv));
            *(uint32_t*)(A1row + SWZ(rEp, 40)) = xp;
        }
        __syncwarp();
    }

    // ---- head: h2 (fp32 copy); FF split by s, combine over lane^2 ----
    const float* W1f = (const float*)(sm + W1F_OFF);
    const float* b1f = (const float*)(sm + B1F_OFF);
    const float* W2f = (const float*)(sm + W2F_OFF);
    const float b2v  = *((const float*)(sm + B2F_OFF));
    float h2f[HID];
#pragma unroll
    for (int k = 0; k < HID; k++) h2f[k] = h2row[k];
    float acc2 = (s == 0) ? b2v : 0.0f;
    const int n0 = s * 32;
#pragma unroll 1
    for (int n = n0; n < n0 + 32; n++) {
        float a = b1f[n];
#pragma unroll
        for (int k = 0; k < HID; k++) a = fmaf(W1f[n * HID + k], h2f[k], a);
        acc2 = fmaf(W2f[n], fmaxf(a, 0.0f), acc2);
    }
    acc2 += __shfl_xor_sync(0xFFFFFFFFu, acc2, 2);
    if (s == 0 && rg < rows) out[rg] = fmaxf(acc2, 0.0f);
}

extern "C" void kernel_launch(void* const* d_in, const int* in_sizes, int n_in,
                              void* d_out, int out_size) {
    const float* diag  = (const float*)d_in[0];
    const float* W_ih1 = (const float*)d_in[1];
    const float* W_hh1 = (const float*)d_in[2];
    const float* b_ih1 = (const float*)d_in[3];
    const float* b_hh1 = (const float*)d_in[4];
    const float* W_ih2 = (const float*)d_in[5];
    const float* W_hh2 = (const float*)d_in[6];
    const float* b_ih2 = (const float*)d_in[7];
    const float* b_hh2 = (const float*)d_in[8];
    const float* W1    = (const float*)d_in[9];
    const float* b1    = (const float*)d_in[10];
    const float* W2    = (const float*)d_in[11];
    const float* b2    = (const float*)d_in[12];

    int rows = out_size;               // 131072
    int blocks = (rows + 127) / 128;   // 1024

    cudaFuncSetAttribute(lstm2_mma_kernel,
                         cudaFuncAttributeMaxDynamicSharedMemorySize, DYN_BYTES);

    lstm2_mma_kernel<<<blocks, 256, DYN_BYTES>>>(
        diag, W_ih1, W_hh1, b_ih1, b_hh1,
        W_ih2, W_hh2, b_ih2, b_hh2,
        W1, b1, W2, b2, (float*)d_out, rows);
}